// round 14
// baseline (speedup 1.0000x reference)
#include <cuda_runtime.h>
#include <cuda_fp16.h>
#include <cstdint>

#define BB   256
#define TT   256
#define KTOK 128
#define HH   512
#define G4H  2048
#define DD   128

#define NCTA 128
#define NTHR 128

#define BG_PITCH 80u                    // 32 gate cols * 2B + 16B pad
#define BO_PITCH 16u                    // 8 cols (2 real + 6 pad) * 2B
#define BO_BUF   8192u

#define BG_OFF  0u
#define BO_OFF  40960u                  // 2 buffers x 8192
#define XG_OFF  57344u
#define SMEM_BYTES 57472u

__device__ __half    g_h[2][BB * HH];
__device__ unsigned  g_cnt[2 * 32];     // per-half arrival counters

__global__ void reset_kernel() { if (threadIdx.x < 64) g_cnt[threadIdx.x] = 0u; }

__device__ __forceinline__ uint32_t smem_u32(const void* p) {
    uint32_t a;
    asm("{ .reg .u64 t; cvta.to.shared.u64 t, %1; cvt.u32.u64 %0, t; }" : "=r"(a) : "l"(p));
    return a;
}
__device__ __forceinline__ float tanha(float x) {
    float r; asm("tanh.approx.f32 %0, %1;" : "=f"(r) : "f"(x)); return r;
}
__device__ __forceinline__ float sigm(float x) { return fmaf(0.5f, tanha(0.5f * x), 0.5f); }

__device__ __forceinline__ void ldsm_x4t(uint32_t* r, uint32_t addr) {
    asm volatile("ldmatrix.sync.aligned.m8n8.x4.trans.shared.b16 {%0,%1,%2,%3}, [%4];"
        : "=r"(r[0]), "=r"(r[1]), "=r"(r[2]), "=r"(r[3]) : "r"(addr));
}
__device__ __forceinline__ void ldsm_x2t(uint32_t* r, uint32_t addr) {
    asm volatile("ldmatrix.sync.aligned.m8n8.x2.trans.shared.b16 {%0,%1}, [%2];"
        : "=r"(r[0]), "=r"(r[1]) : "r"(addr));
}
__device__ __forceinline__ void mma16816(float* d, uint32_t a0, uint32_t a1, uint32_t a2,
                                         uint32_t a3, const uint32_t* b) {
    asm volatile("mma.sync.aligned.m16n8k16.row.col.f32.f16.f16.f32 "
        "{%0,%1,%2,%3}, {%4,%5,%6,%7}, {%8,%9}, {%0,%1,%2,%3};"
        : "+f"(d[0]), "+f"(d[1]), "+f"(d[2]), "+f"(d[3])
        : "r"(a0), "r"(a1), "r"(a2), "r"(a3), "r"(b[0]), "r"(b[1]));
}

// k permutation within 32-blocks (R6, proven): direct LDG.128 -> mma A fragments
__device__ __forceinline__ int vk_to_ak(int vk) {
    int kfl = (vk >> 4) & 1, pair = (vk >> 3) & 1, qc = (vk >> 1) & 3, elem = vk & 1;
    return (vk & ~31) + 8 * qc + kfl * 4 + pair * 2 + elem;
}
__device__ __forceinline__ int ak_to_vk(int ak) {
    int qc = (ak >> 3) & 3, j = ak & 7;
    return (ak & ~31) + (j >> 2) * 16 + ((j >> 1) & 1) * 8 + qc * 2 + (j & 1);
}

__global__ void __launch_bounds__(NTHR, 1) lstm_mma_kernel(
    const float* __restrict__ z,     const float* __restrict__ Wz,
    const float* __restrict__ bz,    const float* __restrict__ token,
    const float* __restrict__ Wi,    const float* __restrict__ Wh,
    const float* __restrict__ bh,    const float* __restrict__ Wout,
    const float* __restrict__ bout,  float* __restrict__ out)
{
    extern __shared__ char smem[];
    const uint32_t sb = smem_u32(smem);

    const int tid  = threadIdx.x;
    const int lane = tid & 31;
    const int w    = tid >> 5;            // warp 0..3 -> rows w*32..w*32+31 (2 m-tiles)
    const int mh   = blockIdx.x & 1;      // batch half (independent sync domain)
    const int jg   = blockIdx.x >> 1;     // unit group 0..63 (8 units)
    const int m0   = mh * 128;
    const int j0   = jg * 8;

    const int qr   = lane >> 2;
    const int qc   = lane & 3;
    const int rbase = w * 32 + qr;        // m-tile m adds m*16; +8 within tile
    const int u0   = qc * 2;

    const uint32_t bgLane = sb + BG_OFF + (uint32_t)(lane & 15) * BG_PITCH
                          + (uint32_t)(lane >> 4) * 16u;
    const uint32_t boLane = sb + BO_OFF + (uint32_t)(lane & 15) * BO_PITCH;

    float* sxg = (float*)(smem + XG_OFF);
    volatile unsigned* myCnt = &g_cnt[mh * 32];

    // ---------------- one-time init ----------------
    for (int i = tid; i < 1024; i += NTHR) ((uint4*)(smem + BO_OFF))[i] = make_uint4(0, 0, 0, 0);

    // Wh slice -> fp16 smem, VIRTUAL k order
    for (int idx = tid; idx < 512 * 32; idx += NTHR) {
        int vk = idx >> 5, n = idx & 31;
        int ak = vk_to_ak(vk);
        float v = __ldg(&Wh[(size_t)ak * G4H + (n >> 3) * HH + j0 + (n & 7)]);
        *(__half*)(smem + BG_OFF + (uint32_t)vk * BG_PITCH + (uint32_t)n * 2u) = __float2half_rn(v);
    }
    if (tid < 32) {
        int col = (tid >> 3) * HH + j0 + (tid & 7);
        float s = bh[col];
        #pragma unroll 4
        for (int k = 0; k < KTOK; ++k)
            s = fmaf(token[k], __ldg(&Wi[(size_t)k * G4H + col]), s);
        sxg[tid] = s;
    }
    {   // h0 = relu(z @ Wz + bz): thread -> row tid, all 8 units
        const int r = tid;
        float a[8];
        #pragma unroll
        for (int q = 0; q < 8; ++q) a[q] = bz[j0 + q];
        const float* zr = z + (size_t)(m0 + r) * KTOK;
        #pragma unroll 4
        for (int k = 0; k < KTOK; ++k) {
            float zv = __ldg(zr + k);
            const float4* wr = (const float4*)&Wz[(size_t)k * HH + j0];
            float4 w0 = __ldg(wr), w1 = __ldg(wr + 1);
            a[0] = fmaf(zv, w0.x, a[0]); a[1] = fmaf(zv, w0.y, a[1]);
            a[2] = fmaf(zv, w0.z, a[2]); a[3] = fmaf(zv, w0.w, a[3]);
            a[4] = fmaf(zv, w1.x, a[4]); a[5] = fmaf(zv, w1.y, a[5]);
            a[6] = fmaf(zv, w1.z, a[6]); a[7] = fmaf(zv, w1.w, a[7]);
        }
        __half2* hp = (__half2*)&g_h[0][(size_t)(m0 + r) * HH + j0];
        #pragma unroll
        for (int q = 0; q < 4; ++q)
            hp[q] = __floats2half2_rn(fmaxf(a[2 * q], 0.f), fmaxf(a[2 * q + 1], 0.f));
    }

    // initial counter barrier (ep = 1)
    unsigned ep = 1;
    __syncthreads();
    if (tid == 0) {
        __threadfence();
        asm volatile("red.global.add.u32 [%0], %1;" :: "l"((unsigned*)myCnt), "r"(1u) : "memory");
        while (*myCnt < ep * 64u) {}
        __threadfence();
    }
    __syncthreads();
    ++ep;

    float c8[2][4];
    #pragma unroll
    for (int m = 0; m < 2; ++m)
        #pragma unroll
        for (int e = 0; e < 4; ++e) c8[m][e] = 0.f;
    float2 wo[4];

    // ---------------- sequential loop ----------------
    #pragma unroll 1
    for (int t = 0; t <= TT; ++t) {
        const __half* hsrc = g_h[t & 1];
        const int te = t - 1;

        // 4 A row-streams: rows rbase + s*8 (s=0,1 -> mtile0; s=2,3 -> mtile1)
        const __half* aBase = hsrc + (size_t)(m0 + rbase) * HH + 8 * qc;
        const uint32_t boSel = boLane + (uint32_t)(t & 1) * BO_BUF;

        // A ring: depth 3 per stream (12 LDG.128 in flight)
        uint4 ar[4][3];
        #pragma unroll
        for (int p = 0; p < 3; ++p)
            #pragma unroll
            for (int s = 0; s < 4; ++s)
                ar[s][p] = __ldcg((const uint4*)(aBase + (size_t)s * 8 * HH + p * 32));

        // prefetch Wout_t for next iteration (overlaps mainloop)
        if (t < TT) {
            const float* Wo = Wout + (size_t)t * HH * DD + jg * 2;
            #pragma unroll
            for (int r = 0; r < 4; ++r)
                wo[r] = __ldcg((const float2*)(Wo + (size_t)(tid * 4 + r) * DD));
        }

        float acc[5][2][4];   // [ntile][mtile][frag]
        #pragma unroll
        for (int n = 0; n < 5; ++n)
            #pragma unroll
            for (int m = 0; m < 2; ++m)
                #pragma unroll
                for (int e = 0; e < 4; ++e) acc[n][m][e] = 0.f;

        #pragma unroll
        for (int b = 0; b < 16; ++b) {
            const int slot = b % 3;
            const uint4 v0 = ar[0][slot], v1 = ar[1][slot],
                        v2 = ar[2][slot], v3 = ar[3][slot];
            if (b + 3 < 16) {
                #pragma unroll
                for (int s = 0; s < 4; ++s)
                    ar[s][slot] = __ldcg((const uint4*)(aBase + (size_t)s * 8 * HH + (b + 3) * 32));
            }
            #pragma unroll
            for (int kfl = 0; kfl < 2; ++kfl) {
                const uint32_t krow = (uint32_t)(b * 32 + kfl * 16);
                uint32_t b1[4], b2[4], b3[2];
                ldsm_x4t(b1, bgLane + krow * BG_PITCH);
                ldsm_x4t(b2, bgLane + krow * BG_PITCH + 32u);
                ldsm_x2t(b3, boSel + krow * BO_PITCH);
                // mtile0 A-frags (streams 0,1)
                const uint32_t a0 = kfl ? v0.z : v0.x, a1 = kfl ? v1.z : v1.x;
                const uint32_t a2 = kfl ? v0.w : v0.y, a3 = kfl ? v1.w : v1.y;
                // mtile1 A-frags (streams 2,3)
                const uint32_t a4 = kfl ? v2.z : v2.x, a5 = kfl ? v3.z : v3.x;
                const uint32_t a6 = kfl ? v2.w : v2.y, a7 = kfl ? v3.w : v3.y;
                mma16816(acc[0][0], a0, a1, a2, a3, b1);
                mma16816(acc[0][1], a4, a5, a6, a7, b1);
                mma16816(acc[1][0], a0, a1, a2, a3, b1 + 2);
                mma16816(acc[1][1], a4, a5, a6, a7, b1 + 2);
                mma16816(acc[2][0], a0, a1, a2, a3, b2);
                mma16816(acc[2][1], a4, a5, a6, a7, b2);
                mma16816(acc[3][0], a0, a1, a2, a3, b2 + 2);
                mma16816(acc[3][1], a4, a5, a6, a7, b2 + 2);
                mma16816(acc[4][0], a0, a1, a2, a3, b3);
                mma16816(acc[4][1], a4, a5, a6, a7, b3);
            }
        }

        // ---- critical path: cell update + h store (both m-tiles) ----
        if (t < TT) {
            __half* hdst = &g_h[(t + 1) & 1][0];
            #pragma unroll
            for (int m = 0; m < 2; ++m) {
                float hv[4];
                #pragma unroll
                for (int e = 0; e < 4; ++e) {
                    const int u = u0 + (e & 1);
                    float gi = sigm (acc[0][m][e] + sxg[u]);
                    float gf = sigm (acc[1][m][e] + sxg[8 + u]);
                    float gg = tanha(acc[2][m][e] + sxg[16 + u]);
                    float go = sigm (acc[3][m][e] + sxg[24 + u]);
                    float cv = gf * c8[m][e] + gi * gg;
                    c8[m][e] = cv;
                    hv[e] = go * tanha(cv);
                }
                const int row = m0 + rbase + m * 16;
                __stcg((__half2*)&hdst[(size_t)row * HH + j0 + u0],
                       __floats2half2_rn(hv[0], hv[1]));
                __stcg((__half2*)&hdst[(size_t)(row + 8) * HH + j0 + u0],
                       __floats2half2_rn(hv[2], hv[3]));
            }
        }

        // ---- barrier arrive ----
        __syncthreads();
        if (t < TT && tid == 0) {
            __threadfence();
            asm volatile("red.global.add.u32 [%0], %1;" :: "l"((unsigned*)myCnt), "r"(1u) : "memory");
        }

        // ---- shadow work: out store + next-step BO staging (alternate buffer) ----
        if (t >= 1 && qc == 0) {
            const float2 bo = *(const float2*)&bout[te * DD + jg * 2];
            #pragma unroll
            for (int m = 0; m < 2; ++m) {
                const int row = m0 + rbase + m * 16;
                *(float2*)&out[(size_t)row * TT * DD + (size_t)te * DD + jg * 2] =
                    make_float2(acc[4][m][0] + bo.x, acc[4][m][1] + bo.y);
                *(float2*)&out[(size_t)(row + 8) * TT * DD + (size_t)te * DD + jg * 2] =
                    make_float2(acc[4][m][2] + bo.x, acc[4][m][3] + bo.y);
            }
        }
        if (t < TT) {
            const uint32_t boNext = BO_OFF + (uint32_t)((t + 1) & 1) * BO_BUF;
            #pragma unroll
            for (int r = 0; r < 4; ++r) {
                __half2 p = __floats2half2_rn(wo[r].x, wo[r].y);
                *(uint32_t*)(smem + boNext + (uint32_t)ak_to_vk(tid * 4 + r) * BO_PITCH) = *(uint32_t*)&p;
            }
        }

        // ---- barrier wait ----
        if (t < TT) {
            if (tid == 0) {
                while (*myCnt < ep * 64u) {}
                __threadfence();
            }
            __syncthreads();
            ++ep;
        }
    }
}

extern "C" void kernel_launch(void* const* d_in, const int* in_sizes, int n_in,
                              void* d_out, int out_size) {
    const float* z     = (const float*)d_in[0];
    const float* Wz    = (const float*)d_in[1];
    const float* bz    = (const float*)d_in[2];
    const float* token = (const float*)d_in[3];
    const float* Wi    = (const float*)d_in[4];
    const float* Wh    = (const float*)d_in[5];
    const float* bh    = (const float*)d_in[6];
    const float* Wout  = (const float*)d_in[7];
    const float* bout  = (const float*)d_in[8];
    float* out = (float*)d_out;

    cudaFuncSetAttribute(lstm_mma_kernel, cudaFuncAttributeMaxDynamicSharedMemorySize, SMEM_BYTES);
    reset_kernel<<<1, 64>>>();
    lstm_mma_kernel<<<NCTA, NTHR, SMEM_BYTES>>>(z, Wz, bz, token, Wi, Wh, bh, Wout, bout, out);
}

// round 16
// speedup vs baseline: 1.2804x; 1.2804x over previous
#include <cuda_runtime.h>
#include <cuda_fp16.h>
#include <cstdint>

#define BB   256
#define TT   256
#define KTOK 128
#define HH   512
#define G4H  2048
#define DD   128

#define NCTAG 128
#define NCTAO 16
#define NCTA  144
#define NTHR  256

#define BG_PITCH 80u                    // 32 gate cols * 2B + 16B pad
#define BG_OFF   0u
#define XG_OFF   40960u
#define WO_OFF   0u                     // out CTAs: 2 x 8KB Wout staging
#define WO_BUF   8192u
#define SMEM_BYTES 41216u

__device__ __half    g_hist[257 * BB * HH];   // h_t for all t (no WAR, out CTAs lag freely)
__device__ unsigned  g_cnt[2 * 32];           // per-half arrival counters

__global__ void reset_kernel() { if (threadIdx.x < 64) g_cnt[threadIdx.x] = 0u; }

__device__ __forceinline__ uint32_t smem_u32(const void* p) {
    uint32_t a;
    asm("{ .reg .u64 t; cvta.to.shared.u64 t, %1; cvt.u32.u64 %0, t; }" : "=r"(a) : "l"(p));
    return a;
}
__device__ __forceinline__ float tanha(float x) {
    float r; asm("tanh.approx.f32 %0, %1;" : "=f"(r) : "f"(x)); return r;
}
__device__ __forceinline__ float sigm(float x) { return fmaf(0.5f, tanha(0.5f * x), 0.5f); }

__device__ __forceinline__ void ldsm_x4t(uint32_t* r, uint32_t addr) {
    asm volatile("ldmatrix.sync.aligned.m8n8.x4.trans.shared.b16 {%0,%1,%2,%3}, [%4];"
        : "=r"(r[0]), "=r"(r[1]), "=r"(r[2]), "=r"(r[3]) : "r"(addr));
}
__device__ __forceinline__ void ldsm_x2t(uint32_t* r, uint32_t addr) {
    asm volatile("ldmatrix.sync.aligned.m8n8.x2.trans.shared.b16 {%0,%1}, [%2];"
        : "=r"(r[0]), "=r"(r[1]) : "r"(addr));
}
__device__ __forceinline__ void mma16816(float* d, uint32_t a0, uint32_t a1, uint32_t a2,
                                         uint32_t a3, const uint32_t* b) {
    asm volatile("mma.sync.aligned.m16n8k16.row.col.f32.f16.f16.f32 "
        "{%0,%1,%2,%3}, {%4,%5,%6,%7}, {%8,%9}, {%0,%1,%2,%3};"
        : "+f"(d[0]), "+f"(d[1]), "+f"(d[2]), "+f"(d[3])
        : "r"(a0), "r"(a1), "r"(a2), "r"(a3), "r"(b[0]), "r"(b[1]));
}
__device__ __forceinline__ uint32_t packh2(float x, float y) {
    __half2 h = __floats2half2_rn(x, y);
    return *(uint32_t*)&h;
}

// k permutation within 32-blocks (R6, proven): direct LDG.128 -> mma A fragments
__device__ __forceinline__ int vk_to_ak(int vk) {
    int kfl = (vk >> 4) & 1, pair = (vk >> 3) & 1, qc = (vk >> 1) & 3, elem = vk & 1;
    return (vk & ~31) + 8 * qc + kfl * 4 + pair * 2 + elem;
}
__device__ __forceinline__ int ak_to_vk(int ak) {
    int qc = (ak >> 3) & 3, j = ak & 7;
    return (ak & ~31) + (j >> 2) * 16 + ((j >> 1) & 1) * 8 + qc * 2 + (j & 1);
}

__global__ void __launch_bounds__(NTHR, 1) lstm_mma_kernel(
    const float* __restrict__ z,     const float* __restrict__ Wz,
    const float* __restrict__ bz,    const float* __restrict__ token,
    const float* __restrict__ Wi,    const float* __restrict__ Wh,
    const float* __restrict__ bh,    const float* __restrict__ Wout,
    const float* __restrict__ bout,  float* __restrict__ out)
{
    extern __shared__ char smem[];
    const uint32_t sb = smem_u32(smem);

    const int tid  = threadIdx.x;
    const int lane = tid & 31;
    const int w    = tid >> 5;
    const int qr   = lane >> 2;
    const int qc   = lane & 3;

    if (blockIdx.x < NCTAG) {
        // ==================== GATE CTA: recurrence only ====================
        const int mh   = blockIdx.x & 1;      // batch half (sync domain)
        const int jg   = blockIdx.x >> 1;     // unit group 0..63 (8 units)
        const int m0   = mh * 128;
        const int j0   = jg * 8;
        const int row0 = w * 16 + qr;
        const int u0   = qc * 2;

        const uint32_t bgLane = sb + BG_OFF + (uint32_t)(lane & 15) * BG_PITCH
                              + (uint32_t)(lane >> 4) * 16u;
        float* sxg = (float*)(smem + XG_OFF);
        volatile unsigned* myCnt = &g_cnt[mh * 32];

        // ---- one-time init ----
        for (int idx = tid; idx < 512 * 32; idx += NTHR) {
            int vk = idx >> 5, n = idx & 31;
            int ak = vk_to_ak(vk);
            float v = __ldg(&Wh[(size_t)ak * G4H + (n >> 3) * HH + j0 + (n & 7)]);
            *(__half*)(smem + BG_OFF + (uint32_t)vk * BG_PITCH + (uint32_t)n * 2u) = __float2half_rn(v);
        }
        if (tid < 32) {
            int col = (tid >> 3) * HH + j0 + (tid & 7);
            float s = bh[col];
            #pragma unroll 4
            for (int k = 0; k < KTOK; ++k)
                s = fmaf(token[k], __ldg(&Wi[(size_t)k * G4H + col]), s);
            sxg[tid] = s;
        }
        {   // h0 = relu(z @ Wz + bz) -> g_hist[0]
            const int r  = tid >> 1;
            const int ub = (tid & 1) * 4;
            float a[4];
            #pragma unroll
            for (int q = 0; q < 4; ++q) a[q] = bz[j0 + ub + q];
            const float* zr = z + (size_t)(m0 + r) * KTOK;
            #pragma unroll 4
            for (int k = 0; k < KTOK; ++k) {
                float zv = __ldg(zr + k);
                float4 w4 = __ldg((const float4*)&Wz[(size_t)k * HH + j0 + ub]);
                a[0] = fmaf(zv, w4.x, a[0]); a[1] = fmaf(zv, w4.y, a[1]);
                a[2] = fmaf(zv, w4.z, a[2]); a[3] = fmaf(zv, w4.w, a[3]);
            }
            __half2* hp = (__half2*)&g_hist[(size_t)(m0 + r) * HH + j0 + ub];
            hp[0] = __floats2half2_rn(fmaxf(a[0], 0.f), fmaxf(a[1], 0.f));
            hp[1] = __floats2half2_rn(fmaxf(a[2], 0.f), fmaxf(a[3], 0.f));
        }

        // initial barrier: publish h0, wait for all 64 CTAs of this half
        __syncthreads();
        if (tid == 0) {
            __threadfence();
            asm volatile("red.global.add.u32 [%0], %1;" :: "l"((unsigned*)myCnt), "r"(1u) : "memory");
            while (*myCnt < 64u) {}
            __threadfence();
        }
        __syncthreads();

        float c4[4] = {0.f, 0.f, 0.f, 0.f};

        #pragma unroll 1
        for (int t = 0; t < TT; ++t) {
            const __half* hsrc = g_hist + (size_t)t * (BB * HH);
            const __half* aRow0 = hsrc + (size_t)(m0 + row0) * HH + 8 * qc;
            const __half* aRow8 = aRow0 + 8 * HH;

            uint4 ra[4], rb[4];
            #pragma unroll
            for (int p = 0; p < 4; ++p) {
                ra[p] = __ldcg((const uint4*)(aRow0 + p * 32));
                rb[p] = __ldcg((const uint4*)(aRow8 + p * 32));
            }

            float acc[4][4];
            #pragma unroll
            for (int n = 0; n < 4; ++n)
                #pragma unroll
                for (int e = 0; e < 4; ++e) acc[n][e] = 0.f;

            #pragma unroll
            for (int b = 0; b < 16; ++b) {
                const int slot = b & 3;
                const uint4 va = ra[slot], vb = rb[slot];
                if (b + 4 < 16) {
                    ra[slot] = __ldcg((const uint4*)(aRow0 + (b + 4) * 32));
                    rb[slot] = __ldcg((const uint4*)(aRow8 + (b + 4) * 32));
                }
                #pragma unroll
                for (int kfl = 0; kfl < 2; ++kfl) {
                    const uint32_t krow = (uint32_t)(b * 32 + kfl * 16);
                    uint32_t b1[4], b2[4];
                    ldsm_x4t(b1, bgLane + krow * BG_PITCH);
                    ldsm_x4t(b2, bgLane + krow * BG_PITCH + 32u);
                    const uint32_t a0 = kfl ? va.z : va.x;
                    const uint32_t a1 = kfl ? vb.z : vb.x;
                    const uint32_t a2 = kfl ? va.w : va.y;
                    const uint32_t a3 = kfl ? vb.w : vb.y;
                    mma16816(acc[0], a0, a1, a2, a3, b1);
                    mma16816(acc[1], a0, a1, a2, a3, b1 + 2);
                    mma16816(acc[2], a0, a1, a2, a3, b2);
                    mma16816(acc[3], a0, a1, a2, a3, b2 + 2);
                }
            }

            // cell update + h_{t+1} store
            {
                __half* hdst = &g_hist[(size_t)(t + 1) * (BB * HH)];
                float hv[4];
                #pragma unroll
                for (int e = 0; e < 4; ++e) {
                    const int u = u0 + (e & 1);
                    float gi = sigm (acc[0][e] + sxg[u]);
                    float gf = sigm (acc[1][e] + sxg[8 + u]);
                    float gg = tanha(acc[2][e] + sxg[16 + u]);
                    float go = sigm (acc[3][e] + sxg[24 + u]);
                    float cv = gf * c4[e] + gi * gg;
                    c4[e] = cv;
                    hv[e] = go * tanha(cv);
                }
                __stcg((__half2*)&hdst[(size_t)(m0 + row0) * HH + j0 + u0],
                       __floats2half2_rn(hv[0], hv[1]));
                __stcg((__half2*)&hdst[(size_t)(m0 + row0 + 8) * HH + j0 + u0],
                       __floats2half2_rn(hv[2], hv[3]));
            }

            __syncthreads();
            if (tid == 0) {
                __threadfence();
                asm volatile("red.global.add.u32 [%0], %1;" :: "l"((unsigned*)myCnt), "r"(1u) : "memory");
            }
            if (t < TT - 1) {
                if (tid == 0) {
                    const unsigned target = 64u * (unsigned)(t + 2);
                    while (*myCnt < target) {}
                    __threadfence();
                }
                __syncthreads();
            }
        }
    } else {
        // ==================== OUT CTA: out_t = h_{t+1} @ Wo_t + bout_t ====================
        const int oid = blockIdx.x - NCTAG;       // 0..15
        const int jd  = oid * 8;                  // 8 D-columns
        const int rbase = (w >> 2) * 128 + (w & 3) * 32 + qr;   // warp rows (2 m-tiles)

        const uint32_t woLane = sb + WO_OFF + (uint32_t)(lane & 15) * 16u;
        volatile unsigned* cnt0 = &g_cnt[0];
        volatile unsigned* cnt1 = &g_cnt[32];

        #pragma unroll 1
        for (int t = 0; t < TT; ++t) {
            const uint32_t buf = (uint32_t)(t & 1) * WO_BUF;

            // stage Wout_t (8 cols, vk row order) -> regs
            const float* Wo = Wout + (size_t)t * HH * DD + jd;
            float4 wa0 = __ldcg((const float4*)(Wo + (size_t)(2 * tid) * DD));
            float4 wa1 = __ldcg((const float4*)(Wo + (size_t)(2 * tid) * DD + 4));
            float4 wb0 = __ldcg((const float4*)(Wo + (size_t)(2 * tid + 1) * DD));
            float4 wb1 = __ldcg((const float4*)(Wo + (size_t)(2 * tid + 1) * DD + 4));

            // wait for h_{t+1} (both halves); gentle poll, single thread
            if (tid == 0) {
                const unsigned target = 64u * (unsigned)(t + 2);
                while (*cnt0 < target || *cnt1 < target) __nanosleep(128);
                __threadfence();
            }

            uint4 pa, pb;
            pa.x = packh2(wa0.x, wa0.y); pa.y = packh2(wa0.z, wa0.w);
            pa.z = packh2(wa1.x, wa1.y); pa.w = packh2(wa1.z, wa1.w);
            pb.x = packh2(wb0.x, wb0.y); pb.y = packh2(wb0.z, wb0.w);
            pb.z = packh2(wb1.x, wb1.y); pb.w = packh2(wb1.z, wb1.w);
            *(uint4*)(smem + WO_OFF + buf + (uint32_t)ak_to_vk(2 * tid) * 16u)     = pa;
            *(uint4*)(smem + WO_OFF + buf + (uint32_t)ak_to_vk(2 * tid + 1) * 16u) = pb;
            __syncthreads();

            const __half* hsrc = g_hist + (size_t)(t + 1) * (BB * HH);
            const __half* aBase = hsrc + (size_t)rbase * HH + 8 * qc;

            uint4 ar[4][3];
            #pragma unroll
            for (int p = 0; p < 3; ++p)
                #pragma unroll
                for (int s = 0; s < 4; ++s)
                    ar[s][p] = __ldcg((const uint4*)(aBase + (size_t)s * 8 * HH + p * 32));

            float acc[2][4];
            #pragma unroll
            for (int m = 0; m < 2; ++m)
                #pragma unroll
                for (int e = 0; e < 4; ++e) acc[m][e] = 0.f;

            #pragma unroll
            for (int b = 0; b < 16; ++b) {
                const int slot = b % 3;
                const uint4 v0 = ar[0][slot], v1 = ar[1][slot],
                            v2 = ar[2][slot], v3 = ar[3][slot];
                if (b + 3 < 16) {
                    #pragma unroll
                    for (int s = 0; s < 4; ++s)
                        ar[s][slot] = __ldcg((const uint4*)(aBase + (size_t)s * 8 * HH + (b + 3) * 32));
                }
                #pragma unroll
                for (int kfl = 0; kfl < 2; ++kfl) {
                    const uint32_t krow = (uint32_t)(b * 32 + kfl * 16);
                    uint32_t bw[2];
                    ldsm_x2t(bw, woLane + buf + krow * 16u);
                    const uint32_t a0 = kfl ? v0.z : v0.x, a1 = kfl ? v1.z : v1.x;
                    const uint32_t a2 = kfl ? v0.w : v0.y, a3 = kfl ? v1.w : v1.y;
                    const uint32_t a4 = kfl ? v2.z : v2.x, a5 = kfl ? v3.z : v3.x;
                    const uint32_t a6 = kfl ? v2.w : v2.y, a7 = kfl ? v3.w : v3.y;
                    mma16816(acc[0], a0, a1, a2, a3, bw);
                    mma16816(acc[1], a4, a5, a6, a7, bw);
                }
            }

            const float2 bo = *(const float2*)&bout[t * DD + jd + 2 * qc];
            #pragma unroll
            for (int m = 0; m < 2; ++m) {
                const int row = rbase + m * 16;
                *(float2*)&out[(size_t)row * TT * DD + (size_t)t * DD + jd + 2 * qc] =
                    make_float2(acc[m][0] + bo.x, acc[m][1] + bo.y);
                *(float2*)&out[(size_t)(row + 8) * TT * DD + (size_t)t * DD + jd + 2 * qc] =
                    make_float2(acc[m][2] + bo.x, acc[m][3] + bo.y);
            }
        }
    }
}

extern "C" void kernel_launch(void* const* d_in, const int* in_sizes, int n_in,
                              void* d_out, int out_size) {
    const float* z     = (const float*)d_in[0];
    const float* Wz    = (const float*)d_in[1];
    const float* bz    = (const float*)d_in[2];
    const float* token = (const float*)d_in[3];
    const float* Wi    = (const float*)d_in[4];
    const float* Wh    = (const float*)d_in[5];
    const float* bh    = (const float*)d_in[6];
    const float* Wout  = (const float*)d_in[7];
    const float* bout  = (const float*)d_in[8];
    float* out = (float*)d_out;

    cudaFuncSetAttribute(lstm_mma_kernel, cudaFuncAttributeMaxDynamicSharedMemorySize, SMEM_BYTES);
    reset_kernel<<<1, 64>>>();
    lstm_mma_kernel<<<NCTA, NTHR, SMEM_BYTES>>>(z, Wz, bz, token, Wi, Wh, bh, Wout, bout, out);
}

// round 17
// speedup vs baseline: 1.3341x; 1.0420x over previous
#include <cuda_runtime.h>
#include <cuda_fp16.h>
#include <cstdint>

#define BB   256
#define TT   256
#define KTOK 128
#define HH   512
#define G4H  2048
#define DD   128

#define NCTAG 128
#define NCTAO 16
#define NCTA  144
#define NTHR  256

#define BG_PITCH 80u                    // 32 gate cols * 2B + 16B pad
#define BG_OFF   0u
#define XG_OFF   40960u
#define WO_OFF   0u                     // out CTAs: 2 x 8KB Wout staging
#define WO_BUF   8192u
#define SMEM_BYTES 41216u

__device__ __half    g_hist[257 * BB * HH];   // h_t for all t (no WAR, out CTAs lag freely)
__device__ unsigned  g_cnt[2 * 8 * 64];       // [half][warp] counters, 256B apart

__global__ void reset_kernel() { if (threadIdx.x < 2 * 8 * 64) g_cnt[threadIdx.x] = 0u; }

__device__ __forceinline__ uint32_t smem_u32(const void* p) {
    uint32_t a;
    asm("{ .reg .u64 t; cvta.to.shared.u64 t, %1; cvt.u32.u64 %0, t; }" : "=r"(a) : "l"(p));
    return a;
}
__device__ __forceinline__ float tanha(float x) {
    float r; asm("tanh.approx.f32 %0, %1;" : "=f"(r) : "f"(x)); return r;
}
__device__ __forceinline__ float sigm(float x) { return fmaf(0.5f, tanha(0.5f * x), 0.5f); }

__device__ __forceinline__ void ldsm_x4t(uint32_t* r, uint32_t addr) {
    asm volatile("ldmatrix.sync.aligned.m8n8.x4.trans.shared.b16 {%0,%1,%2,%3}, [%4];"
        : "=r"(r[0]), "=r"(r[1]), "=r"(r[2]), "=r"(r[3]) : "r"(addr));
}
__device__ __forceinline__ void ldsm_x2t(uint32_t* r, uint32_t addr) {
    asm volatile("ldmatrix.sync.aligned.m8n8.x2.trans.shared.b16 {%0,%1}, [%2];"
        : "=r"(r[0]), "=r"(r[1]) : "r"(addr));
}
__device__ __forceinline__ void mma16816(float* d, uint32_t a0, uint32_t a1, uint32_t a2,
                                         uint32_t a3, const uint32_t* b) {
    asm volatile("mma.sync.aligned.m16n8k16.row.col.f32.f16.f16.f32 "
        "{%0,%1,%2,%3}, {%4,%5,%6,%7}, {%8,%9}, {%0,%1,%2,%3};"
        : "+f"(d[0]), "+f"(d[1]), "+f"(d[2]), "+f"(d[3])
        : "r"(a0), "r"(a1), "r"(a2), "r"(a3), "r"(b[0]), "r"(b[1]));
}
__device__ __forceinline__ uint32_t packh2(float x, float y) {
    __half2 h = __floats2half2_rn(x, y);
    return *(uint32_t*)&h;
}

// k permutation within 32-blocks (R6, proven): direct LDG.128 -> mma A fragments
__device__ __forceinline__ int vk_to_ak(int vk) {
    int kfl = (vk >> 4) & 1, pair = (vk >> 3) & 1, qc = (vk >> 1) & 3, elem = vk & 1;
    return (vk & ~31) + 8 * qc + kfl * 4 + pair * 2 + elem;
}
__device__ __forceinline__ int ak_to_vk(int ak) {
    int qc = (ak >> 3) & 3, j = ak & 7;
    return (ak & ~31) + (j >> 2) * 16 + ((j >> 1) & 1) * 8 + qc * 2 + (j & 1);
}

__global__ void __launch_bounds__(NTHR, 1) lstm_mma_kernel(
    const float* __restrict__ z,     const float* __restrict__ Wz,
    const float* __restrict__ bz,    const float* __restrict__ token,
    const float* __restrict__ Wi,    const float* __restrict__ Wh,
    const float* __restrict__ bh,    const float* __restrict__ Wout,
    const float* __restrict__ bout,  float* __restrict__ out)
{
    extern __shared__ char smem[];
    const uint32_t sb = smem_u32(smem);

    const int tid  = threadIdx.x;
    const int lane = tid & 31;
    const int w    = tid >> 5;
    const int qr   = lane >> 2;
    const int qc   = lane & 3;

    if (blockIdx.x < NCTAG) {
        // ==================== GATE CTA: recurrence only ====================
        const int mh   = blockIdx.x & 1;      // batch half (sync domain)
        const int jg   = blockIdx.x >> 1;     // unit group 0..63 (8 units)
        const int m0   = mh * 128;
        const int j0   = jg * 8;
        const int row0 = w * 16 + qr;
        const int u0   = qc * 2;

        const uint32_t bgLane = sb + BG_OFF + (uint32_t)(lane & 15) * BG_PITCH
                              + (uint32_t)(lane >> 4) * 16u;
        float* sxg = (float*)(smem + XG_OFF);
        unsigned* dom = &g_cnt[mh * 8 * 64];
        unsigned* ownCnt = &dom[w * 64];

        // ---- one-time init ----
        for (int idx = tid; idx < 512 * 32; idx += NTHR) {
            int vk = idx >> 5, n = idx & 31;
            int ak = vk_to_ak(vk);
            float v = __ldg(&Wh[(size_t)ak * G4H + (n >> 3) * HH + j0 + (n & 7)]);
            *(__half*)(smem + BG_OFF + (uint32_t)vk * BG_PITCH + (uint32_t)n * 2u) = __float2half_rn(v);
        }
        if (tid < 32) {
            int col = (tid >> 3) * HH + j0 + (tid & 7);
            float s = bh[col];
            #pragma unroll 4
            for (int k = 0; k < KTOK; ++k)
                s = fmaf(token[k], __ldg(&Wi[(size_t)k * G4H + col]), s);
            sxg[tid] = s;
        }
        {   // h0 = relu(z @ Wz + bz) -> g_hist[0]
            const int r  = tid >> 1;
            const int ub = (tid & 1) * 4;
            float a[4];
            #pragma unroll
            for (int q = 0; q < 4; ++q) a[q] = bz[j0 + ub + q];
            const float* zr = z + (size_t)(m0 + r) * KTOK;
            #pragma unroll 4
            for (int k = 0; k < KTOK; ++k) {
                float zv = __ldg(zr + k);
                float4 w4 = __ldg((const float4*)&Wz[(size_t)k * HH + j0 + ub]);
                a[0] = fmaf(zv, w4.x, a[0]); a[1] = fmaf(zv, w4.y, a[1]);
                a[2] = fmaf(zv, w4.z, a[2]); a[3] = fmaf(zv, w4.w, a[3]);
            }
            __half2* hp = (__half2*)&g_hist[(size_t)(m0 + r) * HH + j0 + ub];
            hp[0] = __floats2half2_rn(fmaxf(a[0], 0.f), fmaxf(a[1], 0.f));
            hp[1] = __floats2half2_rn(fmaxf(a[2], 0.f), fmaxf(a[3], 0.f));
        }

        // initial barrier: CTA-wide h0 staging -> per-warp arrive, warp0 poll
        __syncthreads();
        if (lane == 0) {
            asm volatile("membar.gl;" ::: "memory");
            asm volatile("red.global.add.u32 [%0], %1;" :: "l"(ownCnt), "r"(1u) : "memory");
        }
        if (w == 0) {
            unsigned fv = 64u;
            do {
                if (lane < 8)
                    asm volatile("ld.global.cg.u32 %0, [%1];" : "=r"(fv) : "l"(&dom[lane * 64]));
            } while ((__ballot_sync(0xffffffffu, fv >= 64u) & 0xFFu) != 0xFFu);
            asm volatile("membar.gl;" ::: "memory");
        }
        __syncthreads();

        float c4[4] = {0.f, 0.f, 0.f, 0.f};

        #pragma unroll 1
        for (int t = 0; t < TT; ++t) {
            const __half* hsrc = g_hist + (size_t)t * (BB * HH);
            const __half* aRow0 = hsrc + (size_t)(m0 + row0) * HH + 8 * qc;
            const __half* aRow8 = aRow0 + 8 * HH;

            uint4 ra[4], rb[4];
            #pragma unroll
            for (int p = 0; p < 4; ++p) {
                ra[p] = __ldcg((const uint4*)(aRow0 + p * 32));
                rb[p] = __ldcg((const uint4*)(aRow8 + p * 32));
            }

            float acc[4][4];
            #pragma unroll
            for (int n = 0; n < 4; ++n)
                #pragma unroll
                for (int e = 0; e < 4; ++e) acc[n][e] = 0.f;

            #pragma unroll
            for (int b = 0; b < 16; ++b) {
                const int slot = b & 3;
                const uint4 va = ra[slot], vb = rb[slot];
                if (b + 4 < 16) {
                    ra[slot] = __ldcg((const uint4*)(aRow0 + (b + 4) * 32));
                    rb[slot] = __ldcg((const uint4*)(aRow8 + (b + 4) * 32));
                }
                #pragma unroll
                for (int kfl = 0; kfl < 2; ++kfl) {
                    const uint32_t krow = (uint32_t)(b * 32 + kfl * 16);
                    uint32_t b1[4], b2[4];
                    ldsm_x4t(b1, bgLane + krow * BG_PITCH);
                    ldsm_x4t(b2, bgLane + krow * BG_PITCH + 32u);
                    const uint32_t a0 = kfl ? va.z : va.x;
                    const uint32_t a1 = kfl ? vb.z : vb.x;
                    const uint32_t a2 = kfl ? va.w : va.y;
                    const uint32_t a3 = kfl ? vb.w : vb.y;
                    mma16816(acc[0], a0, a1, a2, a3, b1);
                    mma16816(acc[1], a0, a1, a2, a3, b1 + 2);
                    mma16816(acc[2], a0, a1, a2, a3, b2);
                    mma16816(acc[3], a0, a1, a2, a3, b2 + 2);
                }
            }

            // cell update + h_{t+1} store (warp-local rows) + per-warp publish
            {
                __half* hdst = &g_hist[(size_t)(t + 1) * (BB * HH)];
                float hv[4];
                #pragma unroll
                for (int e = 0; e < 4; ++e) {
                    const int u = u0 + (e & 1);
                    float gi = sigm (acc[0][e] + sxg[u]);
                    float gf = sigm (acc[1][e] + sxg[8 + u]);
                    float gg = tanha(acc[2][e] + sxg[16 + u]);
                    float go = sigm (acc[3][e] + sxg[24 + u]);
                    float cv = gf * c4[e] + gi * gg;
                    c4[e] = cv;
                    hv[e] = go * tanha(cv);
                }
                __stcg((__half2*)&hdst[(size_t)(m0 + row0) * HH + j0 + u0],
                       __floats2half2_rn(hv[0], hv[1]));
                __stcg((__half2*)&hdst[(size_t)(m0 + row0 + 8) * HH + j0 + u0],
                       __floats2half2_rn(hv[2], hv[3]));

                __syncwarp();
                if (lane == 0) {   // publish this warp's rows immediately
                    asm volatile("membar.gl;" ::: "memory");
                    asm volatile("red.global.add.u32 [%0], %1;" :: "l"(ownCnt), "r"(1u) : "memory");
                }
            }

            // wait for h_{t+1} complete (warp0 polls 8 counters; single sync broadcast)
            if (t < TT - 1) {
                const unsigned target = 64u * (unsigned)(t + 2);
                if (w == 0) {
                    unsigned fv = target;
                    do {
                        if (lane < 8)
                            asm volatile("ld.global.cg.u32 %0, [%1];" : "=r"(fv) : "l"(&dom[lane * 64]));
                    } while ((__ballot_sync(0xffffffffu, fv >= target) & 0xFFu) != 0xFFu);
                    asm volatile("membar.gl;" ::: "memory");
                }
                __syncthreads();
            }
        }
    } else {
        // ==================== OUT CTA: out_t = h_{t+1} @ Wo_t + bout_t ====================
        const int oid = blockIdx.x - NCTAG;       // 0..15
        const int jd  = oid * 8;                  // 8 D-columns
        const int rbase = (w >> 2) * 128 + (w & 3) * 32 + qr;   // warp rows (2 m-tiles)

        const uint32_t woLane = sb + WO_OFF + (uint32_t)(lane & 15) * 16u;

        #pragma unroll 1
        for (int t = 0; t < TT; ++t) {
            const uint32_t buf = (uint32_t)(t & 1) * WO_BUF;

            // stage Wout_t (8 cols, vk row order) -> regs
            const float* Wo = Wout + (size_t)t * HH * DD + jd;
            float4 wa0 = __ldcg((const float4*)(Wo + (size_t)(2 * tid) * DD));
            float4 wa1 = __ldcg((const float4*)(Wo + (size_t)(2 * tid) * DD + 4));
            float4 wb0 = __ldcg((const float4*)(Wo + (size_t)(2 * tid + 1) * DD));
            float4 wb1 = __ldcg((const float4*)(Wo + (size_t)(2 * tid + 1) * DD + 4));

            // wait for h_{t+1}: all 16 warp-counters; gentle poll (warp 0, backoff)
            if (w == 0) {
                const unsigned target = 64u * (unsigned)(t + 2);
                unsigned fv = target;
                do {
                    if (lane < 16)
                        asm volatile("ld.global.cg.u32 %0, [%1];" : "=r"(fv)
                                     : "l"(&g_cnt[(lane >> 3) * 8 * 64 + (lane & 7) * 64]));
                    if ((__ballot_sync(0xffffffffu, fv >= target) & 0xFFFFu) == 0xFFFFu) break;
                    __nanosleep(128);
                } while (true);
                asm volatile("membar.gl;" ::: "memory");
            }

            uint4 pa, pb;
            pa.x = packh2(wa0.x, wa0.y); pa.y = packh2(wa0.z, wa0.w);
            pa.z = packh2(wa1.x, wa1.y); pa.w = packh2(wa1.z, wa1.w);
            pb.x = packh2(wb0.x, wb0.y); pb.y = packh2(wb0.z, wb0.w);
            pb.z = packh2(wb1.x, wb1.y); pb.w = packh2(wb1.z, wb1.w);
            *(uint4*)(smem + WO_OFF + buf + (uint32_t)ak_to_vk(2 * tid) * 16u)     = pa;
            *(uint4*)(smem + WO_OFF + buf + (uint32_t)ak_to_vk(2 * tid + 1) * 16u) = pb;
            __syncthreads();

            const __half* hsrc = g_hist + (size_t)(t + 1) * (BB * HH);
            const __half* aBase = hsrc + (size_t)rbase * HH + 8 * qc;

            uint4 ar[4][3];
            #pragma unroll
            for (int p = 0; p < 3; ++p)
                #pragma unroll
                for (int s = 0; s < 4; ++s)
                    ar[s][p] = __ldcg((const uint4*)(aBase + (size_t)s * 8 * HH + p * 32));

            float acc[2][4];
            #pragma unroll
            for (int m = 0; m < 2; ++m)
                #pragma unroll
                for (int e = 0; e < 4; ++e) acc[m][e] = 0.f;

            #pragma unroll
            for (int b = 0; b < 16; ++b) {
                const int slot = b % 3;
                const uint4 v0 = ar[0][slot], v1 = ar[1][slot],
                            v2 = ar[2][slot], v3 = ar[3][slot];
                if (b + 3 < 16) {
                    #pragma unroll
                    for (int s = 0; s < 4; ++s)
                        ar[s][slot] = __ldcg((const uint4*)(aBase + (size_t)s * 8 * HH + (b + 3) * 32));
                }
                #pragma unroll
                for (int kfl = 0; kfl < 2; ++kfl) {
                    const uint32_t krow = (uint32_t)(b * 32 + kfl * 16);
                    uint32_t bw[2];
                    ldsm_x2t(bw, woLane + buf + krow * 16u);
                    const uint32_t a0 = kfl ? v0.z : v0.x, a1 = kfl ? v1.z : v1.x;
                    const uint32_t a2 = kfl ? v0.w : v0.y, a3 = kfl ? v1.w : v1.y;
                    const uint32_t a4 = kfl ? v2.z : v2.x, a5 = kfl ? v3.z : v3.x;
                    const uint32_t a6 = kfl ? v2.w : v2.y, a7 = kfl ? v3.w : v3.y;
                    mma16816(acc[0], a0, a1, a2, a3, bw);
                    mma16816(acc[1], a4, a5, a6, a7, bw);
                }
            }

            const float2 bo = *(const float2*)&bout[t * DD + jd + 2 * qc];
            #pragma unroll
            for (int m = 0; m < 2; ++m) {
                const int row = rbase + m * 16;
                *(float2*)&out[(size_t)row * TT * DD + (size_t)t * DD + jd + 2 * qc] =
                    make_float2(acc[m][0] + bo.x, acc[m][1] + bo.y);
                *(float2*)&out[(size_t)(row + 8) * TT * DD + (size_t)t * DD + jd + 2 * qc] =
                    make_float2(acc[m][2] + bo.x, acc[m][3] + bo.y);
            }
        }
    }
}

extern "C" void kernel_launch(void* const* d_in, const int* in_sizes, int n_in,
                              void* d_out, int out_size) {
    const float* z     = (const float*)d_in[0];
    const float* Wz    = (const float*)d_in[1];
    const float* bz    = (const float*)d_in[2];
    const float* token = (const float*)d_in[3];
    const float* Wi    = (const float*)d_in[4];
    const float* Wh    = (const float*)d_in[5];
    const float* bh    = (const float*)d_in[6];
    const float* Wout  = (const float*)d_in[7];
    const float* bout  = (const float*)d_in[8];
    float* out = (float*)d_out;

    cudaFuncSetAttribute(lstm_mma_kernel, cudaFuncAttributeMaxDynamicSharedMemorySize, SMEM_BYTES);
    reset_kernel<<<1, 1024>>>();
    lstm_mma_kernel<<<NCTA, NTHR, SMEM_BYTES>>>(z, Wz, bz, token, Wi, Wh, bh, Wout, bout, out);
}